// round 5
// baseline (speedup 1.0000x reference)
#include <cuda_runtime.h>

// Problem constants (fixed by the reference)
constexpr int NN = 40000;   // nodes
constexpr int NE = 640000;  // edges
constexpr int DD = 128;     // feature dim
constexpr int NG = 64;      // graphs

constexpr int SCAN_B = 1024;
constexpr int NSCAN  = (NN + SCAN_B) / SCAN_B;  // 40 blocks

// ---------------- scratch (static device globals; no allocations) ----------------
__device__ float g_h  [NN * DD];   // GEMM output (layer1: unscaled; layer2: dinv-scaled)
__device__ float g_x2 [NN * DD];   // layer output buffer
__device__ int   g_deg[NN];        // in-degree (without self loop)
__device__ float g_dinv[NN];       // 1/sqrt(deg+1)
__device__ int   g_rowptr[NN + 1]; // CSR row pointers (by dst)
__device__ int   g_cnt[NN];        // fill cursors
__device__ int   g_csr[NE];        // CSR column indices (src node per edge)
__device__ int   g_bsum[64];       // scan block sums (NSCAN=40 used)

// ---------------- packed f32x2 helpers ----------------
__device__ __forceinline__ void unpack2(unsigned long long v, float& lo, float& hi) {
    asm("mov.b64 {%0, %1}, %2;" : "=f"(lo), "=f"(hi) : "l"(v));
}
__device__ __forceinline__ unsigned long long fma2(unsigned long long a,
                                                   unsigned long long b,
                                                   unsigned long long c) {
    unsigned long long d;
    asm("fma.rn.f32x2 %0, %1, %2, %3;" : "=l"(d) : "l"(a), "l"(b), "l"(c));
    return d;
}

// ---------------- CSR construction ----------------
__global__ void hist_kernel(const int* __restrict__ dst) {
    int i = blockIdx.x * blockDim.x + threadIdx.x;
    if (i < NE) atomicAdd(&g_deg[dst[i]], 1);
}

// Block-level exclusive scan via shuffles (2 syncthreads).
__global__ void __launch_bounds__(SCAN_B) scan1_kernel() {
    __shared__ int wsum[32];
    int tid = threadIdx.x, lane = tid & 31, wid = tid >> 5;
    int i = blockIdx.x * SCAN_B + tid;
    int v = (i < NN) ? g_deg[i] : 0;
    int inc = v;
#pragma unroll
    for (int off = 1; off < 32; off <<= 1) {
        int n = __shfl_up_sync(0xFFFFFFFFu, inc, off);
        if (lane >= off) inc += n;
    }
    if (lane == 31) wsum[wid] = inc;
    __syncthreads();
    if (wid == 0) {
        int s = wsum[lane];
        int si = s;
#pragma unroll
        for (int off = 1; off < 32; off <<= 1) {
            int n = __shfl_up_sync(0xFFFFFFFFu, si, off);
            if (lane >= off) si += n;
        }
        wsum[lane] = si - s;  // exclusive warp offsets
    }
    __syncthreads();
    int excl = inc - v + wsum[wid];
    if (i <= NN) g_rowptr[i] = excl;
    if (tid == SCAN_B - 1) g_bsum[blockIdx.x] = excl + v;
}

// Adds cross-block offsets (block-sum prefix computed in-kernel), writes
// final rowptr, fill cursors, and dinv. Replaces the old scan2+scan3 pair.
__global__ void __launch_bounds__(256) scan3_kernel() {
    __shared__ int s_off;
    int tid = threadIdx.x;
    int i = blockIdx.x * 256 + tid;
    int blk = blockIdx.x >> 2;  // 256 | 1024, so all i in this block share one scan-block
    if (tid < 32) {
        int a = (tid < blk) ? g_bsum[tid] : 0;
        if (tid + 32 < blk) a += g_bsum[tid + 32];
#pragma unroll
        for (int off = 16; off; off >>= 1) a += __shfl_down_sync(0xFFFFFFFFu, a, off);
        if (tid == 0) s_off = a;
    }
    __syncthreads();
    if (i <= NN) {
        int rp = g_rowptr[i] + s_off;
        g_rowptr[i] = rp;
        if (i < NN) {
            g_cnt[i]  = rp;
            g_dinv[i] = rsqrtf((float)(g_deg[i] + 1));  // +1: self loop
        }
    }
}

__global__ void fill_kernel(const int* __restrict__ src, const int* __restrict__ dst) {
    int i = blockIdx.x * blockDim.x + threadIdx.x;
    if (i < NE) {
        int slot = atomicAdd(&g_cnt[dst[i]], 1);
        g_csr[slot] = src[i];
    }
}

// ---------------- GEMM: g_h = [dinv[row] *] (A @ W) ----------------
// Block tile 128x128, 256 threads, 8x8 per thread, K-blocked by 16.
// A tile stored DUPLICATED in smem ((a,a) pairs) so the mainloop reads f32x2
// operands directly — no per-k pack MOVs.
// SEL==0: A = param (the input x). SEL==1: A = g_x2.
constexpr int AS_STRIDE = 260;  // floats per k-row; 260*4 % 16 == 0, %32==4 (2-way store conflicts)

template <int SEL, bool SCALE>
__global__ void __launch_bounds__(256) gemm_kernel(const float* __restrict__ Ain,
                                                   const float* __restrict__ W) {
    const float* A = (SEL == 0) ? Ain : (const float*)g_x2;
    __shared__ float As[16][AS_STRIDE];  // duplicated, transposed A tile
    __shared__ float Bs[16][128];        // W tile

    int tid = threadIdx.x;
    int tx = tid & 15;    // output cols tx*4..+3 and tx*4+64..+3
    int ty = tid >> 4;    // output rows ty*8..+7
    int rowBase = blockIdx.x * 128;

    unsigned long long acc2[8][4];
#pragma unroll
    for (int i = 0; i < 8; i++)
#pragma unroll
        for (int j = 0; j < 4; j++) acc2[i][j] = 0ull;

    for (int kt = 0; kt < 128; kt += 16) {
        // load A tile (128 rows x 16 k), transposed + duplicated into As[k][2m,2m+1]
#pragma unroll
        for (int l = 0; l < 2; l++) {
            int idx = tid + l * 256;       // 0..511
            int r   = idx >> 2;            // 0..127
            int k4  = (idx & 3) << 2;      // 0,4,8,12
            float4 v = make_float4(0.f, 0.f, 0.f, 0.f);
            int gr = rowBase + r;
            if (gr < NN) v = *(const float4*)(A + gr * 128 + kt + k4);
            *(float2*)&As[k4 + 0][2 * r] = make_float2(v.x, v.x);
            *(float2*)&As[k4 + 1][2 * r] = make_float2(v.y, v.y);
            *(float2*)&As[k4 + 2][2 * r] = make_float2(v.z, v.z);
            *(float2*)&As[k4 + 3][2 * r] = make_float2(v.w, v.w);
        }
        // load W tile (16 k x 128 n)
#pragma unroll
        for (int l = 0; l < 2; l++) {
            int idx = tid + l * 256;
            int kk  = idx >> 5;            // 0..15
            int n4  = (idx & 31) << 2;     // 0..124
            *(float4*)&Bs[kk][n4] = *(const float4*)(W + (kt + kk) * 128 + n4);
        }
        __syncthreads();

#pragma unroll
        for (int k = 0; k < 16; k++) {
            // a: 8 duplicated pairs = 16 floats = 4 x LDS.128 (broadcast across warp)
            const ulonglong2* ap = (const ulonglong2*)&As[k][ty * 16];
            ulonglong2 p0 = ap[0], p1 = ap[1], p2 = ap[2], p3 = ap[3];
            unsigned long long ad[8] = {p0.x, p0.y, p1.x, p1.y, p2.x, p2.y, p3.x, p3.y};
            // b: 8 floats as 4 packed f32x2 (two LDS.128)
            ulonglong2 bp0 = *(const ulonglong2*)&Bs[k][tx * 4];
            ulonglong2 bp1 = *(const ulonglong2*)&Bs[k][tx * 4 + 64];
            unsigned long long bd[4] = {bp0.x, bp0.y, bp1.x, bp1.y};
#pragma unroll
            for (int i = 0; i < 8; i++)
#pragma unroll
                for (int j = 0; j < 4; j++)
                    acc2[i][j] = fma2(ad[i], bd[j], acc2[i][j]);
        }
        __syncthreads();
    }

    // epilogue
#pragma unroll
    for (int i = 0; i < 8; i++) {
        int gr = rowBase + ty * 8 + i;
        if (gr < NN) {
            float s = SCALE ? g_dinv[gr] : 1.0f;
            float o[8];
#pragma unroll
            for (int j = 0; j < 4; j++) {
                float lo, hi;
                unpack2(acc2[i][j], lo, hi);
                o[2 * j]     = lo * s;
                o[2 * j + 1] = hi * s;
            }
            *(float4*)(g_h + gr * 128 + tx * 4)      = make_float4(o[0], o[1], o[2], o[3]);
            *(float4*)(g_h + gr * 128 + tx * 4 + 64) = make_float4(o[4], o[5], o[6], o[7]);
        }
    }
}

// ---------------- aggregation: warp per node ----------------
// SRCSCALE=true : g_h unscaled; out[i] = f( dinv[i]*(dinv[i]*h[i] + sum dinv[j]*h[j]) + b )
// SRCSCALE=false: g_h pre-scaled; out[i] = f( dinv[i]*(hs[i] + sum hs[j]) + b )
template <bool RELU, bool SRCSCALE>
__global__ void __launch_bounds__(256) agg_kernel(const float* __restrict__ bias) {
    int w    = (blockIdx.x * blockDim.x + threadIdx.x) >> 5;
    int lane = threadIdx.x & 31;
    if (w >= NN) return;

    int beg = g_rowptr[w];
    int end = g_rowptr[w + 1];
    float dv = g_dinv[w];

    const float4* hv = (const float4*)g_h;
    float4 self = hv[w * 32 + lane];
    float4 acc;
    if (SRCSCALE) {
        acc = make_float4(self.x * dv, self.y * dv, self.z * dv, self.w * dv);
    } else {
        acc = self;
    }

    int k = beg;
    for (; k + 3 < end; k += 4) {
        int s0 = g_csr[k];
        int s1 = g_csr[k + 1];
        int s2 = g_csr[k + 2];
        int s3 = g_csr[k + 3];
        float4 v0 = hv[s0 * 32 + lane];
        float4 v1 = hv[s1 * 32 + lane];
        float4 v2 = hv[s2 * 32 + lane];
        float4 v3 = hv[s3 * 32 + lane];
        if (SRCSCALE) {
            float d0 = __ldg(&g_dinv[s0]);
            float d1 = __ldg(&g_dinv[s1]);
            float d2 = __ldg(&g_dinv[s2]);
            float d3 = __ldg(&g_dinv[s3]);
            acc.x = fmaf(v0.x, d0, acc.x); acc.y = fmaf(v0.y, d0, acc.y);
            acc.z = fmaf(v0.z, d0, acc.z); acc.w = fmaf(v0.w, d0, acc.w);
            acc.x = fmaf(v1.x, d1, acc.x); acc.y = fmaf(v1.y, d1, acc.y);
            acc.z = fmaf(v1.z, d1, acc.z); acc.w = fmaf(v1.w, d1, acc.w);
            acc.x = fmaf(v2.x, d2, acc.x); acc.y = fmaf(v2.y, d2, acc.y);
            acc.z = fmaf(v2.z, d2, acc.z); acc.w = fmaf(v2.w, d2, acc.w);
            acc.x = fmaf(v3.x, d3, acc.x); acc.y = fmaf(v3.y, d3, acc.y);
            acc.z = fmaf(v3.z, d3, acc.z); acc.w = fmaf(v3.w, d3, acc.w);
        } else {
            acc.x += v0.x + v1.x + v2.x + v3.x;
            acc.y += v0.y + v1.y + v2.y + v3.y;
            acc.z += v0.z + v1.z + v2.z + v3.z;
            acc.w += v0.w + v1.w + v2.w + v3.w;
        }
    }
    for (; k < end; k++) {
        int s = g_csr[k];
        float4 v = hv[s * 32 + lane];
        if (SRCSCALE) {
            float d = __ldg(&g_dinv[s]);
            acc.x = fmaf(v.x, d, acc.x); acc.y = fmaf(v.y, d, acc.y);
            acc.z = fmaf(v.z, d, acc.z); acc.w = fmaf(v.w, d, acc.w);
        } else {
            acc.x += v.x; acc.y += v.y; acc.z += v.z; acc.w += v.w;
        }
    }

    float4 bb = ((const float4*)bias)[lane];
    float4 r;
    r.x = fmaf(dv, acc.x, bb.x);
    r.y = fmaf(dv, acc.y, bb.y);
    r.z = fmaf(dv, acc.z, bb.z);
    r.w = fmaf(dv, acc.w, bb.w);
    if (RELU) {
        r.x = fmaxf(r.x, 0.f);
        r.y = fmaxf(r.y, 0.f);
        r.z = fmaxf(r.z, 0.f);
        r.w = fmaxf(r.w, 0.f);
    }
    ((float4*)g_x2)[w * 32 + lane] = r;
}

// ---------------- pooling: one block per graph, 512 threads ----------------
__device__ __forceinline__ int lower_bound_dev(const int* a, int n, int key) {
    int lo = 0, hi = n;
    while (lo < hi) {
        int mid = (lo + hi) >> 1;
        if (a[mid] < key) lo = mid + 1; else hi = mid;
    }
    return lo;
}

__global__ void __launch_bounds__(512) pool_kernel(const int* __restrict__ batch,
                                                   float* __restrict__ out) {
    __shared__ int s_lo, s_hi;
    __shared__ float red[4][128];
    int g = blockIdx.x;
    int t = threadIdx.x;
    int f   = t & 127;   // feature
    int seg = t >> 7;    // row slice 0..3
    if (t == 0) {
        s_lo = lower_bound_dev(batch, NN, g);
        s_hi = lower_bound_dev(batch, NN, g + 1);
    }
    __syncthreads();
    int lo = s_lo, hi = s_hi;
    float sum = 0.f;
    for (int r = lo + seg; r < hi; r += 4) sum += g_x2[r * 128 + f];
    red[seg][f] = sum;
    __syncthreads();
    if (seg == 0) {
        float c = (float)(hi - lo);
        float tot = red[0][f] + red[1][f] + red[2][f] + red[3][f];
        out[g * 128 + f] = tot / fmaxf(c, 1.0f);
    }
}

// ---------------- launch ----------------
extern "C" void kernel_launch(void* const* d_in, const int* in_sizes, int n_in,
                              void* d_out, int out_size) {
    const float* x     = (const float*)d_in[0];
    const int*   ei    = (const int*)d_in[1];   // [2, E] row-major
    const int*   batch = (const int*)d_in[2];
    const float* W1    = (const float*)d_in[3];
    const float* b1    = (const float*)d_in[4];
    const float* W2    = (const float*)d_in[5];
    const float* b2    = (const float*)d_in[6];
    float* out = (float*)d_out;

    const int* src = ei;        // edge_index[0]
    const int* dst = ei + NE;   // edge_index[1]

    // One-time host resources (streams/events are not device memory).
    static cudaStream_t s2 = nullptr;
    static cudaEvent_t evFork = nullptr, evJoin = nullptr;
    static void* degPtr = nullptr;
    if (s2 == nullptr) {
        cudaStreamCreateWithFlags(&s2, cudaStreamNonBlocking);
        cudaEventCreateWithFlags(&evFork, cudaEventDisableTiming);
        cudaEventCreateWithFlags(&evJoin, cudaEventDisableTiming);
        cudaGetSymbolAddress(&degPtr, g_deg);
    }

    // Fork: GEMM-1 (no dependence on edges/dinv) runs on s2 while the CSR
    // build runs on the main stream.
    cudaEventRecord(evFork, 0);
    cudaStreamWaitEvent(s2, evFork, 0);
    gemm_kernel<0, false><<<(NN + 127) / 128, 256, 0, s2>>>(x, W1);
    cudaEventRecord(evJoin, s2);

    // CSR build (by destination) + dinv, on main stream
    cudaMemsetAsync(degPtr, 0, NN * sizeof(int), 0);
    hist_kernel<<<(NE + 255) / 256, 256>>>(dst);
    scan1_kernel<<<NSCAN, SCAN_B>>>();
    scan3_kernel<<<(NN + 1 + 255) / 256, 256>>>();
    fill_kernel<<<(NE + 255) / 256, 256>>>(src, dst);

    // Join: aggregation needs both GEMM-1 output and the CSR.
    cudaStreamWaitEvent(0, evJoin, 0);

    // Layer 1 aggregation: applies dinv[src] per edge (g_h unscaled) + relu
    agg_kernel<true, true><<<(NN + 7) / 8, 256>>>(b1);

    // Layer 2: hs = dinv * (x2 @ W2); x2 = dinv*(hs_self + sum hs_nbr) + b2
    gemm_kernel<1, true><<<(NN + 127) / 128, 256>>>(nullptr, W2);
    agg_kernel<false, false><<<(NN + 7) / 8, 256>>>(b2);

    // Global mean pool
    pool_kernel<<<NG, 512>>>(batch, out);
}

// round 6
// speedup vs baseline: 1.1806x; 1.1806x over previous
#include <cuda_runtime.h>

// Problem constants (fixed by the reference)
constexpr int NN = 40000;   // nodes
constexpr int NE = 640000;  // edges
constexpr int DD = 128;     // feature dim
constexpr int NG = 64;      // graphs

constexpr int SCAN_B = 1024;
constexpr int NSCAN  = (NN + SCAN_B) / SCAN_B;  // 40 blocks

// ---------------- scratch (static device globals; no allocations) ----------------
__device__ float g_h  [NN * DD];   // GEMM output (layer1: unscaled; layer2: dinv-scaled)
__device__ float g_x2 [NN * DD];   // layer output buffer
__device__ int   g_deg[NN];        // in-degree (without self loop)
__device__ float g_dinv[NN];       // 1/sqrt(deg+1)
__device__ int   g_rowptr[NN + 1]; // CSR row pointers (by dst)
__device__ int   g_cnt[NN];        // fill cursors
__device__ int   g_csr[NE];        // CSR column indices (src node per edge)
__device__ int   g_bsum[64];       // scan block sums (NSCAN=40 used)

// ---------------- packed f32x2 helpers ----------------
__device__ __forceinline__ unsigned long long pack2(float lo, float hi) {
    unsigned long long r;
    asm("mov.b64 %0, {%1, %2};" : "=l"(r) : "f"(lo), "f"(hi));
    return r;
}
__device__ __forceinline__ void unpack2(unsigned long long v, float& lo, float& hi) {
    asm("mov.b64 {%0, %1}, %2;" : "=f"(lo), "=f"(hi) : "l"(v));
}
__device__ __forceinline__ unsigned long long fma2(unsigned long long a,
                                                   unsigned long long b,
                                                   unsigned long long c) {
    unsigned long long d;
    asm("fma.rn.f32x2 %0, %1, %2, %3;" : "=l"(d) : "l"(a), "l"(b), "l"(c));
    return d;
}

// ---------------- CSR construction ----------------
__global__ void hist_kernel(const int* __restrict__ dst) {
    int i = blockIdx.x * blockDim.x + threadIdx.x;
    if (i < NE) atomicAdd(&g_deg[dst[i]], 1);
}

// Block-level exclusive scan via shuffles (2 syncthreads).
__global__ void __launch_bounds__(SCAN_B) scan1_kernel() {
    __shared__ int wsum[32];
    int tid = threadIdx.x, lane = tid & 31, wid = tid >> 5;
    int i = blockIdx.x * SCAN_B + tid;
    int v = (i < NN) ? g_deg[i] : 0;
    int inc = v;
#pragma unroll
    for (int off = 1; off < 32; off <<= 1) {
        int n = __shfl_up_sync(0xFFFFFFFFu, inc, off);
        if (lane >= off) inc += n;
    }
    if (lane == 31) wsum[wid] = inc;
    __syncthreads();
    if (wid == 0) {
        int s = wsum[lane];
        int si = s;
#pragma unroll
        for (int off = 1; off < 32; off <<= 1) {
            int n = __shfl_up_sync(0xFFFFFFFFu, si, off);
            if (lane >= off) si += n;
        }
        wsum[lane] = si - s;  // exclusive warp offsets
    }
    __syncthreads();
    int excl = inc - v + wsum[wid];
    if (i <= NN) g_rowptr[i] = excl;
    if (tid == SCAN_B - 1) g_bsum[blockIdx.x] = excl + v;
}

// Adds cross-block offsets (block-sum prefix computed in-kernel), writes
// final rowptr, fill cursors, and dinv.
__global__ void __launch_bounds__(256) scan3_kernel() {
    __shared__ int s_off;
    int tid = threadIdx.x;
    int i = blockIdx.x * 256 + tid;
    int blk = blockIdx.x >> 2;  // 1024 = 4*256: all i in this block share one scan-block
    if (tid < 32) {
        int a = (tid < blk) ? g_bsum[tid] : 0;
        if (tid + 32 < blk) a += g_bsum[tid + 32];
#pragma unroll
        for (int off = 16; off; off >>= 1) a += __shfl_down_sync(0xFFFFFFFFu, a, off);
        if (tid == 0) s_off = a;
    }
    __syncthreads();
    if (i <= NN) {
        int rp = g_rowptr[i] + s_off;
        g_rowptr[i] = rp;
        if (i < NN) {
            g_cnt[i]  = rp;
            g_dinv[i] = rsqrtf((float)(g_deg[i] + 1));  // +1: self loop
        }
    }
}

__global__ void fill_kernel(const int* __restrict__ src, const int* __restrict__ dst) {
    int i = blockIdx.x * blockDim.x + threadIdx.x;
    if (i < NE) {
        int slot = atomicAdd(&g_cnt[dst[i]], 1);
        g_csr[slot] = src[i];
    }
}

// ---------------- GEMM: g_h = [dinv[row] *] (A @ W) ----------------
// R4-proven config: block tile 128x128, 256 threads, 8x8 per thread,
// K-blocked by 16, packed fma.rn.f32x2 mainloop, AS stride 132.
// SEL==0: A = param (the input x). SEL==1: A = g_x2.
template <int SEL, bool SCALE>
__global__ void __launch_bounds__(256) gemm_kernel(const float* __restrict__ Ain,
                                                   const float* __restrict__ W) {
    const float* A = (SEL == 0) ? Ain : (const float*)g_x2;
    __shared__ float As[16][132];  // transposed A tile; stride 132 keeps 16B alignment
    __shared__ float Bs[16][128];  // W tile

    int tid = threadIdx.x;
    int tx = tid & 15;    // output cols tx*4..+3 and tx*4+64..+3
    int ty = tid >> 4;    // output rows ty*8..+7
    int rowBase = blockIdx.x * 128;

    unsigned long long acc2[8][4];
#pragma unroll
    for (int i = 0; i < 8; i++)
#pragma unroll
        for (int j = 0; j < 4; j++) acc2[i][j] = 0ull;

    for (int kt = 0; kt < 128; kt += 16) {
        // load A tile (128 rows x 16 k), transposed into As[k][m]
#pragma unroll
        for (int l = 0; l < 2; l++) {
            int idx = tid + l * 256;       // 0..511
            int r   = idx >> 2;            // 0..127
            int k4  = (idx & 3) << 2;      // 0,4,8,12
            float4 v = make_float4(0.f, 0.f, 0.f, 0.f);
            int gr = rowBase + r;
            if (gr < NN) v = *(const float4*)(A + gr * 128 + kt + k4);
            As[k4 + 0][r] = v.x;
            As[k4 + 1][r] = v.y;
            As[k4 + 2][r] = v.z;
            As[k4 + 3][r] = v.w;
        }
        // load W tile (16 k x 128 n)
#pragma unroll
        for (int l = 0; l < 2; l++) {
            int idx = tid + l * 256;
            int kk  = idx >> 5;            // 0..15
            int n4  = (idx & 31) << 2;     // 0..124
            *(float4*)&Bs[kk][n4] = *(const float4*)(W + (kt + kk) * 128 + n4);
        }
        __syncthreads();

#pragma unroll
        for (int k = 0; k < 16; k++) {
            // a: 8 contiguous floats (two LDS.128), duplicated into f32x2 lanes
            float4 a0 = *(const float4*)&As[k][ty * 8];
            float4 a1 = *(const float4*)&As[k][ty * 8 + 4];
            unsigned long long ad[8];
            ad[0] = pack2(a0.x, a0.x); ad[1] = pack2(a0.y, a0.y);
            ad[2] = pack2(a0.z, a0.z); ad[3] = pack2(a0.w, a0.w);
            ad[4] = pack2(a1.x, a1.x); ad[5] = pack2(a1.y, a1.y);
            ad[6] = pack2(a1.z, a1.z); ad[7] = pack2(a1.w, a1.w);
            // b: 8 floats as 4 packed f32x2 (two LDS.128)
            ulonglong2 bp0 = *(const ulonglong2*)&Bs[k][tx * 4];
            ulonglong2 bp1 = *(const ulonglong2*)&Bs[k][tx * 4 + 64];
            unsigned long long bd[4] = {bp0.x, bp0.y, bp1.x, bp1.y};
#pragma unroll
            for (int i = 0; i < 8; i++)
#pragma unroll
                for (int j = 0; j < 4; j++)
                    acc2[i][j] = fma2(ad[i], bd[j], acc2[i][j]);
        }
        __syncthreads();
    }

    // epilogue
#pragma unroll
    for (int i = 0; i < 8; i++) {
        int gr = rowBase + ty * 8 + i;
        if (gr < NN) {
            float s = SCALE ? g_dinv[gr] : 1.0f;
            float o[8];
#pragma unroll
            for (int j = 0; j < 4; j++) {
                float lo, hi;
                unpack2(acc2[i][j], lo, hi);
                o[2 * j]     = lo * s;
                o[2 * j + 1] = hi * s;
            }
            *(float4*)(g_h + gr * 128 + tx * 4)      = make_float4(o[0], o[1], o[2], o[3]);
            *(float4*)(g_h + gr * 128 + tx * 4 + 64) = make_float4(o[4], o[5], o[6], o[7]);
        }
    }
}

// ---------------- aggregation: warp per node ----------------
// SRCSCALE=true : g_h unscaled; out[i] = f( dinv[i]*(dinv[i]*h[i] + sum dinv[j]*h[j]) + b )
// SRCSCALE=false: g_h pre-scaled; out[i] = f( dinv[i]*(hs[i] + sum hs[j]) + b )
template <bool RELU, bool SRCSCALE>
__global__ void __launch_bounds__(256) agg_kernel(const float* __restrict__ bias) {
    int w    = (blockIdx.x * blockDim.x + threadIdx.x) >> 5;
    int lane = threadIdx.x & 31;
    if (w >= NN) return;

    int beg = g_rowptr[w];
    int end = g_rowptr[w + 1];
    float dv = g_dinv[w];

    const float4* hv = (const float4*)g_h;
    float4 self = hv[w * 32 + lane];
    float4 acc;
    if (SRCSCALE) {
        acc = make_float4(self.x * dv, self.y * dv, self.z * dv, self.w * dv);
    } else {
        acc = self;
    }

    int k = beg;
    for (; k + 3 < end; k += 4) {
        int s0 = g_csr[k];
        int s1 = g_csr[k + 1];
        int s2 = g_csr[k + 2];
        int s3 = g_csr[k + 3];
        float4 v0 = hv[s0 * 32 + lane];
        float4 v1 = hv[s1 * 32 + lane];
        float4 v2 = hv[s2 * 32 + lane];
        float4 v3 = hv[s3 * 32 + lane];
        if (SRCSCALE) {
            float d0 = __ldg(&g_dinv[s0]);
            float d1 = __ldg(&g_dinv[s1]);
            float d2 = __ldg(&g_dinv[s2]);
            float d3 = __ldg(&g_dinv[s3]);
            acc.x = fmaf(v0.x, d0, acc.x); acc.y = fmaf(v0.y, d0, acc.y);
            acc.z = fmaf(v0.z, d0, acc.z); acc.w = fmaf(v0.w, d0, acc.w);
            acc.x = fmaf(v1.x, d1, acc.x); acc.y = fmaf(v1.y, d1, acc.y);
            acc.z = fmaf(v1.z, d1, acc.z); acc.w = fmaf(v1.w, d1, acc.w);
            acc.x = fmaf(v2.x, d2, acc.x); acc.y = fmaf(v2.y, d2, acc.y);
            acc.z = fmaf(v2.z, d2, acc.z); acc.w = fmaf(v2.w, d2, acc.w);
            acc.x = fmaf(v3.x, d3, acc.x); acc.y = fmaf(v3.y, d3, acc.y);
            acc.z = fmaf(v3.z, d3, acc.z); acc.w = fmaf(v3.w, d3, acc.w);
        } else {
            acc.x += v0.x + v1.x + v2.x + v3.x;
            acc.y += v0.y + v1.y + v2.y + v3.y;
            acc.z += v0.z + v1.z + v2.z + v3.z;
            acc.w += v0.w + v1.w + v2.w + v3.w;
        }
    }
    for (; k < end; k++) {
        int s = g_csr[k];
        float4 v = hv[s * 32 + lane];
        if (SRCSCALE) {
            float d = __ldg(&g_dinv[s]);
            acc.x = fmaf(v.x, d, acc.x); acc.y = fmaf(v.y, d, acc.y);
            acc.z = fmaf(v.z, d, acc.z); acc.w = fmaf(v.w, d, acc.w);
        } else {
            acc.x += v.x; acc.y += v.y; acc.z += v.z; acc.w += v.w;
        }
    }

    float4 bb = ((const float4*)bias)[lane];
    float4 r;
    r.x = fmaf(dv, acc.x, bb.x);
    r.y = fmaf(dv, acc.y, bb.y);
    r.z = fmaf(dv, acc.z, bb.z);
    r.w = fmaf(dv, acc.w, bb.w);
    if (RELU) {
        r.x = fmaxf(r.x, 0.f);
        r.y = fmaxf(r.y, 0.f);
        r.z = fmaxf(r.z, 0.f);
        r.w = fmaxf(r.w, 0.f);
    }
    ((float4*)g_x2)[w * 32 + lane] = r;
}

// ---------------- pooling: one block per graph, 512 threads ----------------
__device__ __forceinline__ int lower_bound_dev(const int* a, int n, int key) {
    int lo = 0, hi = n;
    while (lo < hi) {
        int mid = (lo + hi) >> 1;
        if (a[mid] < key) lo = mid + 1; else hi = mid;
    }
    return lo;
}

__global__ void __launch_bounds__(512) pool_kernel(const int* __restrict__ batch,
                                                   float* __restrict__ out) {
    __shared__ int s_lo, s_hi;
    __shared__ float red[4][128];
    int g = blockIdx.x;
    int t = threadIdx.x;
    int f   = t & 127;   // feature
    int seg = t >> 7;    // row slice 0..3
    if (t == 0) {
        s_lo = lower_bound_dev(batch, NN, g);
        s_hi = lower_bound_dev(batch, NN, g + 1);
    }
    __syncthreads();
    int lo = s_lo, hi = s_hi;
    float sum = 0.f;
    for (int r = lo + seg; r < hi; r += 4) sum += g_x2[r * 128 + f];
    red[seg][f] = sum;
    __syncthreads();
    if (seg == 0) {
        float c = (float)(hi - lo);
        float tot = red[0][f] + red[1][f] + red[2][f] + red[3][f];
        out[g * 128 + f] = tot / fmaxf(c, 1.0f);
    }
}

// ---------------- launch ----------------
extern "C" void kernel_launch(void* const* d_in, const int* in_sizes, int n_in,
                              void* d_out, int out_size) {
    const float* x     = (const float*)d_in[0];
    const int*   ei    = (const int*)d_in[1];   // [2, E] row-major
    const int*   batch = (const int*)d_in[2];
    const float* W1    = (const float*)d_in[3];
    const float* b1    = (const float*)d_in[4];
    const float* W2    = (const float*)d_in[5];
    const float* b2    = (const float*)d_in[6];
    float* out = (float*)d_out;

    const int* src = ei;        // edge_index[0]
    const int* dst = ei + NE;   // edge_index[1]

    // One-time host resources (streams/events are not device memory).
    static cudaStream_t s2 = nullptr;
    static cudaEvent_t evFork = nullptr, evJoin = nullptr;
    static void* degPtr = nullptr;
    if (s2 == nullptr) {
        cudaStreamCreateWithFlags(&s2, cudaStreamNonBlocking);
        cudaEventCreateWithFlags(&evFork, cudaEventDisableTiming);
        cudaEventCreateWithFlags(&evJoin, cudaEventDisableTiming);
        cudaGetSymbolAddress(&degPtr, g_deg);
    }

    // Fork: GEMM-1 (no dependence on edges/dinv) runs on s2 while the CSR
    // build runs on the main stream.
    cudaEventRecord(evFork, 0);
    cudaStreamWaitEvent(s2, evFork, 0);
    gemm_kernel<0, false><<<(NN + 127) / 128, 256, 0, s2>>>(x, W1);
    cudaEventRecord(evJoin, s2);

    // CSR build (by destination) + dinv, on main stream
    cudaMemsetAsync(degPtr, 0, NN * sizeof(int), 0);
    hist_kernel<<<(NE + 255) / 256, 256>>>(dst);
    scan1_kernel<<<NSCAN, SCAN_B>>>();
    scan3_kernel<<<(NN + 1 + 255) / 256, 256>>>();
    fill_kernel<<<(NE + 255) / 256, 256>>>(src, dst);

    // Join: aggregation needs both GEMM-1 output and the CSR.
    cudaStreamWaitEvent(0, evJoin, 0);

    // Layer 1 aggregation: applies dinv[src] per edge (g_h unscaled) + relu
    agg_kernel<true, true><<<(NN + 7) / 8, 256>>>(b1);

    // Layer 2: hs = dinv * (x2 @ W2); x2 = dinv*(hs_self + sum hs_nbr) + b2
    gemm_kernel<1, true><<<(NN + 127) / 128, 256>>>(nullptr, W2);
    agg_kernel<false, false><<<(NN + 7) / 8, 256>>>(b2);

    // Global mean pool
    pool_kernel<<<NG, 512>>>(batch, out);
}

// round 7
// speedup vs baseline: 1.5114x; 1.2801x over previous
#include <cuda_runtime.h>

// Problem constants (fixed by the reference)
constexpr int NN = 40000;   // nodes
constexpr int NE = 640000;  // edges
constexpr int DD = 128;     // feature dim
constexpr int NG = 64;      // graphs

constexpr int SCAN_B = 1024;
constexpr int NSCAN  = (NN + SCAN_B) / SCAN_B;  // 40 blocks

// ---------------- scratch (static device globals; no allocations) ----------------
__device__ float g_h  [NN * DD];   // ping: gemm1 out (unscaled), later agg2 out
__device__ float g_x2 [NN * DD];   // pong: agg1 out (dinv-prescaled relu)
__device__ float g_z  [NG * DD];   // pooled per-graph means
__device__ int   g_deg[NN];        // in-degree (without self loop)
__device__ float g_dinv[NN];       // 1/sqrt(deg+1)
__device__ int   g_rowptr[NN + 1]; // CSR row pointers (by dst)
__device__ int   g_cnt[NN];        // fill cursors
__device__ int   g_csr[NE];        // CSR column indices (src node per edge)
__device__ int   g_bsum[64];       // scan block sums (NSCAN=40 used)

// ---------------- packed f32x2 helpers ----------------
__device__ __forceinline__ unsigned long long pack2(float lo, float hi) {
    unsigned long long r;
    asm("mov.b64 %0, {%1, %2};" : "=l"(r) : "f"(lo), "f"(hi));
    return r;
}
__device__ __forceinline__ void unpack2(unsigned long long v, float& lo, float& hi) {
    asm("mov.b64 {%0, %1}, %2;" : "=f"(lo), "=f"(hi) : "l"(v));
}
__device__ __forceinline__ unsigned long long fma2(unsigned long long a,
                                                   unsigned long long b,
                                                   unsigned long long c) {
    unsigned long long d;
    asm("fma.rn.f32x2 %0, %1, %2, %3;" : "=l"(d) : "l"(a), "l"(b), "l"(c));
    return d;
}

// ---------------- CSR construction ----------------
__global__ void hist_kernel(const int* __restrict__ dst) {
    int i = blockIdx.x * blockDim.x + threadIdx.x;
    if (i < NE) atomicAdd(&g_deg[dst[i]], 1);
}

// Block-level exclusive scan via shuffles (2 syncthreads).
__global__ void __launch_bounds__(SCAN_B) scan1_kernel() {
    __shared__ int wsum[32];
    int tid = threadIdx.x, lane = tid & 31, wid = tid >> 5;
    int i = blockIdx.x * SCAN_B + tid;
    int v = (i < NN) ? g_deg[i] : 0;
    int inc = v;
#pragma unroll
    for (int off = 1; off < 32; off <<= 1) {
        int n = __shfl_up_sync(0xFFFFFFFFu, inc, off);
        if (lane >= off) inc += n;
    }
    if (lane == 31) wsum[wid] = inc;
    __syncthreads();
    if (wid == 0) {
        int s = wsum[lane];
        int si = s;
#pragma unroll
        for (int off = 1; off < 32; off <<= 1) {
            int n = __shfl_up_sync(0xFFFFFFFFu, si, off);
            if (lane >= off) si += n;
        }
        wsum[lane] = si - s;  // exclusive warp offsets
    }
    __syncthreads();
    int excl = inc - v + wsum[wid];
    if (i <= NN) g_rowptr[i] = excl;
    if (tid == SCAN_B - 1) g_bsum[blockIdx.x] = excl + v;
}

// Adds cross-block offsets (block-sum prefix computed in-kernel), writes
// final rowptr, fill cursors, and dinv.
__global__ void __launch_bounds__(256) scan3_kernel() {
    __shared__ int s_off;
    int tid = threadIdx.x;
    int i = blockIdx.x * 256 + tid;
    int blk = blockIdx.x >> 2;  // 1024 = 4*256: all i in this block share one scan-block
    if (tid < 32) {
        int a = (tid < blk) ? g_bsum[tid] : 0;
        if (tid + 32 < blk) a += g_bsum[tid + 32];
#pragma unroll
        for (int off = 16; off; off >>= 1) a += __shfl_down_sync(0xFFFFFFFFu, a, off);
        if (tid == 0) s_off = a;
    }
    __syncthreads();
    if (i <= NN) {
        int rp = g_rowptr[i] + s_off;
        g_rowptr[i] = rp;
        if (i < NN) {
            g_cnt[i]  = rp;
            g_dinv[i] = rsqrtf((float)(g_deg[i] + 1));  // +1: self loop
        }
    }
}

__global__ void fill_kernel(const int* __restrict__ src, const int* __restrict__ dst) {
    int i = blockIdx.x * blockDim.x + threadIdx.x;
    if (i < NE) {
        int slot = atomicAdd(&g_cnt[dst[i]], 1);
        g_csr[slot] = src[i];
    }
}

// ---------------- GEMM-1: g_h = x @ W1 (unscaled) ----------------
// R4-proven config: block tile 128x128, 256 threads, 8x8 per thread,
// K-blocked by 16, packed fma.rn.f32x2 mainloop, AS stride 132.
__global__ void __launch_bounds__(256) gemm_kernel(const float* __restrict__ A,
                                                   const float* __restrict__ W) {
    __shared__ float As[16][132];  // transposed A tile; stride 132 keeps 16B alignment
    __shared__ float Bs[16][128];  // W tile

    int tid = threadIdx.x;
    int tx = tid & 15;    // output cols tx*4..+3 and tx*4+64..+3
    int ty = tid >> 4;    // output rows ty*8..+7
    int rowBase = blockIdx.x * 128;

    unsigned long long acc2[8][4];
#pragma unroll
    for (int i = 0; i < 8; i++)
#pragma unroll
        for (int j = 0; j < 4; j++) acc2[i][j] = 0ull;

    for (int kt = 0; kt < 128; kt += 16) {
        // load A tile (128 rows x 16 k), transposed into As[k][m]
#pragma unroll
        for (int l = 0; l < 2; l++) {
            int idx = tid + l * 256;       // 0..511
            int r   = idx >> 2;            // 0..127
            int k4  = (idx & 3) << 2;      // 0,4,8,12
            float4 v = make_float4(0.f, 0.f, 0.f, 0.f);
            int gr = rowBase + r;
            if (gr < NN) v = *(const float4*)(A + gr * 128 + kt + k4);
            As[k4 + 0][r] = v.x;
            As[k4 + 1][r] = v.y;
            As[k4 + 2][r] = v.z;
            As[k4 + 3][r] = v.w;
        }
        // load W tile (16 k x 128 n)
#pragma unroll
        for (int l = 0; l < 2; l++) {
            int idx = tid + l * 256;
            int kk  = idx >> 5;            // 0..15
            int n4  = (idx & 31) << 2;     // 0..124
            *(float4*)&Bs[kk][n4] = *(const float4*)(W + (kt + kk) * 128 + n4);
        }
        __syncthreads();

#pragma unroll
        for (int k = 0; k < 16; k++) {
            // a: 8 contiguous floats (two LDS.128), duplicated into f32x2 lanes
            float4 a0 = *(const float4*)&As[k][ty * 8];
            float4 a1 = *(const float4*)&As[k][ty * 8 + 4];
            unsigned long long ad[8];
            ad[0] = pack2(a0.x, a0.x); ad[1] = pack2(a0.y, a0.y);
            ad[2] = pack2(a0.z, a0.z); ad[3] = pack2(a0.w, a0.w);
            ad[4] = pack2(a1.x, a1.x); ad[5] = pack2(a1.y, a1.y);
            ad[6] = pack2(a1.z, a1.z); ad[7] = pack2(a1.w, a1.w);
            // b: 8 floats as 4 packed f32x2 (two LDS.128)
            ulonglong2 bp0 = *(const ulonglong2*)&Bs[k][tx * 4];
            ulonglong2 bp1 = *(const ulonglong2*)&Bs[k][tx * 4 + 64];
            unsigned long long bd[4] = {bp0.x, bp0.y, bp1.x, bp1.y};
#pragma unroll
            for (int i = 0; i < 8; i++)
#pragma unroll
                for (int j = 0; j < 4; j++)
                    acc2[i][j] = fma2(ad[i], bd[j], acc2[i][j]);
        }
        __syncthreads();
    }

    // epilogue (unscaled store)
#pragma unroll
    for (int i = 0; i < 8; i++) {
        int gr = rowBase + ty * 8 + i;
        if (gr < NN) {
            float o[8];
#pragma unroll
            for (int j = 0; j < 4; j++) {
                float lo, hi;
                unpack2(acc2[i][j], lo, hi);
                o[2 * j]     = lo;
                o[2 * j + 1] = hi;
            }
            *(float4*)(g_h + gr * 128 + tx * 4)      = make_float4(o[0], o[1], o[2], o[3]);
            *(float4*)(g_h + gr * 128 + tx * 4 + 64) = make_float4(o[4], o[5], o[6], o[7]);
        }
    }
}

// ---------------- aggregation: warp per node ----------------
// LAYER==1: in = g_h (unscaled h1). Per edge multiplies dinv[src]; computes
//           x2 = relu(dinv_i*(dinv_i*h_i + sum dinv_j*h_j) + b1), stores
//           dinv_i * x2 into g_x2 (pre-scaled for the next aggregation).
// LAYER==2: in = g_x2 (pre-scaled). Computes y_i = dinv_i*(x2s_i + sum x2s_j),
//           NO bias, stores to g_h.
template <int LAYER>
__global__ void __launch_bounds__(256) agg_kernel(const float* __restrict__ bias) {
    int w    = (blockIdx.x * blockDim.x + threadIdx.x) >> 5;
    int lane = threadIdx.x & 31;
    if (w >= NN) return;

    int beg = g_rowptr[w];
    int end = g_rowptr[w + 1];
    float dv = g_dinv[w];

    const float4* hv = (LAYER == 1) ? (const float4*)g_h : (const float4*)g_x2;
    float4 self = hv[w * 32 + lane];
    float4 acc;
    if (LAYER == 1) {
        acc = make_float4(self.x * dv, self.y * dv, self.z * dv, self.w * dv);
    } else {
        acc = self;
    }

    int k = beg;
    for (; k + 3 < end; k += 4) {
        int s0 = g_csr[k];
        int s1 = g_csr[k + 1];
        int s2 = g_csr[k + 2];
        int s3 = g_csr[k + 3];
        float4 v0 = hv[s0 * 32 + lane];
        float4 v1 = hv[s1 * 32 + lane];
        float4 v2 = hv[s2 * 32 + lane];
        float4 v3 = hv[s3 * 32 + lane];
        if (LAYER == 1) {
            float d0 = __ldg(&g_dinv[s0]);
            float d1 = __ldg(&g_dinv[s1]);
            float d2 = __ldg(&g_dinv[s2]);
            float d3 = __ldg(&g_dinv[s3]);
            acc.x = fmaf(v0.x, d0, acc.x); acc.y = fmaf(v0.y, d0, acc.y);
            acc.z = fmaf(v0.z, d0, acc.z); acc.w = fmaf(v0.w, d0, acc.w);
            acc.x = fmaf(v1.x, d1, acc.x); acc.y = fmaf(v1.y, d1, acc.y);
            acc.z = fmaf(v1.z, d1, acc.z); acc.w = fmaf(v1.w, d1, acc.w);
            acc.x = fmaf(v2.x, d2, acc.x); acc.y = fmaf(v2.y, d2, acc.y);
            acc.z = fmaf(v2.z, d2, acc.z); acc.w = fmaf(v2.w, d2, acc.w);
            acc.x = fmaf(v3.x, d3, acc.x); acc.y = fmaf(v3.y, d3, acc.y);
            acc.z = fmaf(v3.z, d3, acc.z); acc.w = fmaf(v3.w, d3, acc.w);
        } else {
            acc.x += v0.x + v1.x + v2.x + v3.x;
            acc.y += v0.y + v1.y + v2.y + v3.y;
            acc.z += v0.z + v1.z + v2.z + v3.z;
            acc.w += v0.w + v1.w + v2.w + v3.w;
        }
    }
    for (; k < end; k++) {
        int s = g_csr[k];
        float4 v = hv[s * 32 + lane];
        if (LAYER == 1) {
            float d = __ldg(&g_dinv[s]);
            acc.x = fmaf(v.x, d, acc.x); acc.y = fmaf(v.y, d, acc.y);
            acc.z = fmaf(v.z, d, acc.z); acc.w = fmaf(v.w, d, acc.w);
        } else {
            acc.x += v.x; acc.y += v.y; acc.z += v.z; acc.w += v.w;
        }
    }

    float4 r;
    if (LAYER == 1) {
        float4 bb = ((const float4*)bias)[lane];
        r.x = fmaf(dv, acc.x, bb.x);
        r.y = fmaf(dv, acc.y, bb.y);
        r.z = fmaf(dv, acc.z, bb.z);
        r.w = fmaf(dv, acc.w, bb.w);
        // relu then pre-scale by dinv_i for the next aggregation
        r.x = fmaxf(r.x, 0.f) * dv;
        r.y = fmaxf(r.y, 0.f) * dv;
        r.z = fmaxf(r.z, 0.f) * dv;
        r.w = fmaxf(r.w, 0.f) * dv;
        ((float4*)g_x2)[w * 32 + lane] = r;
    } else {
        r.x = dv * acc.x;
        r.y = dv * acc.y;
        r.z = dv * acc.z;
        r.w = dv * acc.w;
        ((float4*)g_h)[w * 32 + lane] = r;
    }
}

// ---------------- pooling: one block per graph, 512 threads ----------------
__device__ __forceinline__ int lower_bound_dev(const int* a, int n, int key) {
    int lo = 0, hi = n;
    while (lo < hi) {
        int mid = (lo + hi) >> 1;
        if (a[mid] < key) lo = mid + 1; else hi = mid;
    }
    return lo;
}

__global__ void __launch_bounds__(512) pool_kernel(const int* __restrict__ batch) {
    __shared__ int s_lo, s_hi;
    __shared__ float red[4][128];
    int g = blockIdx.x;
    int t = threadIdx.x;
    int f   = t & 127;   // feature
    int seg = t >> 7;    // row slice 0..3
    if (t == 0) {
        s_lo = lower_bound_dev(batch, NN, g);
        s_hi = lower_bound_dev(batch, NN, g + 1);
    }
    __syncthreads();
    int lo = s_lo, hi = s_hi;
    float sum = 0.f;
    for (int r = lo + seg; r < hi; r += 4) sum += g_h[r * 128 + f];
    red[seg][f] = sum;
    __syncthreads();
    if (seg == 0) {
        float c = (float)(hi - lo);
        float tot = red[0][f] + red[1][f] + red[2][f] + red[3][f];
        g_z[g * 128 + f] = tot / fmaxf(c, 1.0f);
    }
}

// ---------------- final micro-GEMM: out = z @ W2 + b2  (64x128x128) ----------------
__global__ void __launch_bounds__(128) out_gemm_kernel(const float* __restrict__ W2,
                                                       const float* __restrict__ b2,
                                                       float* __restrict__ out) {
    __shared__ float zrow[128];
    int g = blockIdx.x;
    int f = threadIdx.x;
    zrow[f] = g_z[g * 128 + f];
    __syncthreads();
    float acc = b2[f];
#pragma unroll 8
    for (int k = 0; k < 128; k++) acc = fmaf(zrow[k], W2[k * 128 + f], acc);
    out[g * 128 + f] = acc;
}

// ---------------- launch ----------------
extern "C" void kernel_launch(void* const* d_in, const int* in_sizes, int n_in,
                              void* d_out, int out_size) {
    const float* x     = (const float*)d_in[0];
    const int*   ei    = (const int*)d_in[1];   // [2, E] row-major
    const int*   batch = (const int*)d_in[2];
    const float* W1    = (const float*)d_in[3];
    const float* b1    = (const float*)d_in[4];
    const float* W2    = (const float*)d_in[5];
    const float* b2    = (const float*)d_in[6];
    float* out = (float*)d_out;

    const int* src = ei;        // edge_index[0]
    const int* dst = ei + NE;   // edge_index[1]

    // One-time host resources (streams/events are not device memory).
    static cudaStream_t s2 = nullptr;
    static cudaEvent_t evFork = nullptr, evJoin = nullptr;
    static void* degPtr = nullptr;
    if (s2 == nullptr) {
        cudaStreamCreateWithFlags(&s2, cudaStreamNonBlocking);
        cudaEventCreateWithFlags(&evFork, cudaEventDisableTiming);
        cudaEventCreateWithFlags(&evJoin, cudaEventDisableTiming);
        cudaGetSymbolAddress(&degPtr, g_deg);
    }

    // Fork: GEMM-1 (no dependence on edges/dinv) runs on s2 while the CSR
    // build runs on the main stream.
    cudaEventRecord(evFork, 0);
    cudaStreamWaitEvent(s2, evFork, 0);
    gemm_kernel<<<(NN + 127) / 128, 256, 0, s2>>>(x, W1);
    cudaEventRecord(evJoin, s2);

    // CSR build (by destination) + dinv, on main stream
    cudaMemsetAsync(degPtr, 0, NN * sizeof(int), 0);
    hist_kernel<<<(NE + 255) / 256, 256>>>(dst);
    scan1_kernel<<<NSCAN, SCAN_B>>>();
    scan3_kernel<<<(NN + 1 + 255) / 256, 256>>>();
    fill_kernel<<<(NE + 255) / 256, 256>>>(src, dst);

    // Join: aggregation needs both GEMM-1 output and the CSR.
    cudaStreamWaitEvent(0, evJoin, 0);

    // Layer 1 aggregation (+relu, +b1), writes dinv-prescaled x2 to g_x2.
    agg_kernel<1><<<(NN + 7) / 8, 256>>>(b1);

    // Layer 2 aggregation only (W2 commuted past S and pooling), writes g_h.
    agg_kernel<2><<<(NN + 7) / 8, 256>>>(nullptr);

    // Global mean pool -> z[64,128]
    pool_kernel<<<NG, 512>>>(batch);

    // out = z @ W2 + b2
    out_gemm_kernel<<<NG, DD>>>(W2, b2, out);
}